// round 2
// baseline (speedup 1.0000x reference)
#include <cuda_runtime.h>
#include <math.h>

#define NTOK 16384
#define DD   1024
#define HH   4096
#define OO   1024
#define EE   8
#define NBANDS 4
#define RR   16
#define SCALING 2.0f
#define MAXP 33280          // 2N padded: 32768 + 8*64
#define RT_MAX (MAXP/64)    // 520 row tiles

// ---------------- scratch (device globals; no runtime allocation) ------------
__device__ int   g_e0[NTOK], g_e1[NTOK];
__device__ float g_g0[NTOK], g_g1[NTOK];
__device__ int   g_cnt[EE];
__device__ int   g_offPad[EE + 1];
__device__ int   g_cursor[EE];
__device__ int   g_pairTok[MAXP];
__device__ int   g_pairBand[MAXP];
__device__ int   g_pairExp[MAXP];
__device__ float g_pairGate[MAXP];
__device__ float g_r1[MAXP * RR];
__device__ float g_s2[MAXP * RR];
__device__ float g_h[(size_t)MAXP * HH];   // ~545 MB gelu(h) buffer

__device__ __forceinline__ float gelu_exact(float v) {
    return 0.5f * v * (1.0f + erff(v * 0.70710678118654752f));
}

// ---------------- init: zero y (and any tail incl. loss slot) ----------------
__global__ void k_init(float* __restrict__ y, int out_size) {
    int i = blockIdx.x * 256 + threadIdx.x;
    if (i < out_size) y[i] = 0.f;
    if (i < EE) g_cnt[i] = 0;
}

// ---------------- gating: one warp per token ---------------------------------
__global__ void k_gate(const float* __restrict__ x, const float* __restrict__ wg) {
    int tok  = blockIdx.x * 4 + (threadIdx.x >> 5);
    int lane = threadIdx.x & 31;
    if (tok >= NTOK) return;
    const float* xr = x + (size_t)tok * DD;
    float acc[EE];
#pragma unroll
    for (int e = 0; e < EE; e++) acc[e] = 0.f;
    for (int d = lane; d < DD; d += 32) {
        float xv = xr[d];
        const float* w = wg + d * EE;
#pragma unroll
        for (int e = 0; e < EE; e++) acc[e] += xv * w[e];
    }
#pragma unroll
    for (int e = 0; e < EE; e++)
#pragma unroll
        for (int o = 16; o > 0; o >>= 1) acc[e] += __shfl_xor_sync(0xffffffffu, acc[e], o);
    if (lane == 0) {
        int e0 = 0; float v0 = acc[0];
#pragma unroll
        for (int e = 1; e < EE; e++) if (acc[e] > v0) { v0 = acc[e]; e0 = e; }
        int e1 = -1; float v1 = -INFINITY;
#pragma unroll
        for (int e = 0; e < EE; e++) if (e != e0 && acc[e] > v1) { v1 = acc[e]; e1 = e; }
        float z1 = expf(v1 - v0);          // v0 >= v1
        float den = 1.0f + z1;
        float g0 = 1.0f / den, g1 = z1 / den;
        g_e0[tok] = e0; g_e1[tok] = e1; g_g0[tok] = g0; g_g1[tok] = g1;
        atomicAdd(&g_cnt[e0], 1);
        atomicAdd(&g_cnt[e1], 1);
    }
}

// ---------------- loss: deterministic tree reduction -------------------------
__global__ void k_loss(float* __restrict__ out, int out_size) {
    __shared__ float s[EE * 256];
    float acc[EE];
#pragma unroll
    for (int e = 0; e < EE; e++) acc[e] = 0.f;
    for (int t = threadIdx.x; t < NTOK; t += 256) {
        int e0 = g_e0[t], e1 = g_e1[t];
        float g0 = g_g0[t], g1 = g_g1[t];
#pragma unroll
        for (int e = 0; e < EE; e++)
            acc[e] += (e == e0 ? g0 : 0.f) + (e == e1 ? g1 : 0.f);
    }
#pragma unroll
    for (int e = 0; e < EE; e++) s[e * 256 + threadIdx.x] = acc[e];
    __syncthreads();
    for (int st = 128; st > 0; st >>= 1) {
        if (threadIdx.x < st) {
#pragma unroll
            for (int e = 0; e < EE; e++)
                s[e * 256 + threadIdx.x] += s[e * 256 + threadIdx.x + st];
        }
        __syncthreads();
    }
    if (threadIdx.x == 0) {
        float imp[EE], ld[EE];
#pragma unroll
        for (int e = 0; e < EE; e++) { imp[e] = s[e * 256]; ld[e] = (float)g_cnt[e]; }
        float m1 = 0.f, m2 = 0.f;
#pragma unroll
        for (int e = 0; e < EE; e++) { m1 += imp[e]; m2 += ld[e]; }
        m1 /= EE; m2 /= EE;
        float v1 = 0.f, v2 = 0.f;
#pragma unroll
        for (int e = 0; e < EE; e++) {
            float d1 = imp[e] - m1, d2 = ld[e] - m2;
            v1 += d1 * d1; v2 += d2 * d2;
        }
        v1 /= (EE - 1); v2 /= (EE - 1);
        float cv1 = v1 / (m1 * m1 + 1e-10f);
        float cv2 = v2 / (m2 * m2 + 1e-10f);
        out[out_size - 1] = 0.01f * (cv1 + cv2);
    }
}

// ---------------- dispatch prep + scatter ------------------------------------
__global__ void k_prep() {
    int i = blockIdx.x * 256 + threadIdx.x;
    if (i < MAXP) {
        g_pairTok[i] = -1; g_pairExp[i] = 0; g_pairBand[i] = 0; g_pairGate[i] = 0.f;
    }
    if (i == 0) {
        int off = 0;
        for (int e = 0; e < EE; e++) {
            g_offPad[e] = off;
            g_cursor[e] = off;
            off += ((g_cnt[e] + 63) >> 6) << 6;
        }
        g_offPad[EE] = off;
    }
}

__global__ void k_scatter(const int* __restrict__ band) {
    int t = blockIdx.x * 256 + threadIdx.x;
    if (t >= NTOK) return;
    int b = band[t];
    int e0 = g_e0[t];
    int p0 = atomicAdd(&g_cursor[e0], 1);
    g_pairTok[p0] = t; g_pairExp[p0] = e0; g_pairBand[p0] = b; g_pairGate[p0] = g_g0[t];
    int e1 = g_e1[t];
    int p1 = atomicAdd(&g_cursor[e1], 1);
    g_pairTok[p1] = t; g_pairExp[p1] = e1; g_pairBand[p1] = b; g_pairGate[p1] = g_g1[t];
}

// ---------------- r1 = x . A1[e][band] : one warp per pair -------------------
__global__ void k_r1(const float* __restrict__ x, const float* __restrict__ A1) {
    int p    = blockIdx.x * 4 + (threadIdx.x >> 5);
    int lane = threadIdx.x & 31;
    if (p >= MAXP) return;
    int tok = g_pairTok[p];
    if (tok < 0) {
        if (lane == 0)
            for (int r = 0; r < RR; r++) g_r1[p * RR + r] = 0.f;
        return;
    }
    int e = g_pairExp[p], b = g_pairBand[p];
    const float* A  = A1 + (size_t)(e * NBANDS + b) * DD * RR;
    const float* xr = x + (size_t)tok * DD;
    float acc[RR];
#pragma unroll
    for (int r = 0; r < RR; r++) acc[r] = 0.f;
    for (int d = lane; d < DD; d += 32) {
        float xv = xr[d];
        const float4* Ar = (const float4*)(A + (size_t)d * RR);
#pragma unroll
        for (int q = 0; q < 4; q++) {
            float4 av = Ar[q];
            acc[q * 4 + 0] += xv * av.x;
            acc[q * 4 + 1] += xv * av.y;
            acc[q * 4 + 2] += xv * av.z;
            acc[q * 4 + 3] += xv * av.w;
        }
    }
#pragma unroll
    for (int r = 0; r < RR; r++)
#pragma unroll
        for (int o = 16; o > 0; o >>= 1) acc[r] += __shfl_xor_sync(0xffffffffu, acc[r], o);
    if (lane == 0)
        for (int r = 0; r < RR; r++) g_r1[p * RR + r] = acc[r];
}

// ---------------- pass 1: h = gelu(x@W1 + b1 + 2*r1@B1) ----------------------
__global__ void __launch_bounds__(256) k_mlp1(const float* __restrict__ x,
                                              const float* __restrict__ W1,
                                              const float* __restrict__ b1,
                                              const float* __restrict__ B1) {
    __shared__ float As[16 * 68];
    __shared__ float Bs[16 * 64];
    __shared__ int   sTok[64];
    __shared__ int   sBand[64];
    __shared__ float sR1[64 * RR];

    int row0 = blockIdx.x * 64;
    if (row0 >= g_offPad[EE]) return;
    int e = 0;
#pragma unroll
    for (int i = 1; i < EE; i++) if (row0 >= g_offPad[i]) e = i;
    int j0  = blockIdx.y * 64;
    int tid = threadIdx.x;

    if (tid < 64) {
        int p = row0 + tid;
        sTok[tid]  = g_pairTok[p];
        sBand[tid] = g_pairBand[p];
    }
    for (int i = tid; i < 64 * RR; i += 256) sR1[i] = g_r1[(size_t)row0 * RR + i];
    __syncthreads();

    int ty = tid >> 4, tx = tid & 15;
    float acc[4][4];
#pragma unroll
    for (int i = 0; i < 4; i++)
#pragma unroll
        for (int j = 0; j < 4; j++) acc[i][j] = 0.f;

    int pp = tid >> 2;
    int kq = tid & 3;
    int tokL = sTok[pp];
    const float* Wbase = W1 + (size_t)e * DD * HH + j0;
    int brow = tid >> 4;
    int bcol = (tid & 15) * 4;

    for (int k0 = 0; k0 < DD; k0 += 16) {
        float4 av = make_float4(0.f, 0.f, 0.f, 0.f);
        if (tokL >= 0) av = *(const float4*)(x + (size_t)tokL * DD + k0 + kq * 4);
        int kb = kq * 4;
        As[(kb + 0) * 68 + pp] = av.x;
        As[(kb + 1) * 68 + pp] = av.y;
        As[(kb + 2) * 68 + pp] = av.z;
        As[(kb + 3) * 68 + pp] = av.w;
        float4 bv = *(const float4*)(Wbase + (size_t)(k0 + brow) * HH + bcol);
        *(float4*)&Bs[brow * 64 + bcol] = bv;
        __syncthreads();
#pragma unroll
        for (int kk = 0; kk < 16; kk++) {
            float4 a = *(const float4*)&As[kk * 68 + ty * 4];
            float4 b = *(const float4*)&Bs[kk * 64 + tx * 4];
            acc[0][0] += a.x * b.x; acc[0][1] += a.x * b.y; acc[0][2] += a.x * b.z; acc[0][3] += a.x * b.w;
            acc[1][0] += a.y * b.x; acc[1][1] += a.y * b.y; acc[1][2] += a.y * b.z; acc[1][3] += a.y * b.w;
            acc[2][0] += a.z * b.x; acc[2][1] += a.z * b.y; acc[2][2] += a.z * b.z; acc[2][3] += a.z * b.w;
            acc[3][0] += a.w * b.x; acc[3][1] += a.w * b.y; acc[3][2] += a.w * b.z; acc[3][3] += a.w * b.w;
        }
        __syncthreads();
    }

#pragma unroll
    for (int i = 0; i < 4; i++) {
        int p    = ty * 4 + i;
        int band = sBand[p];
        const float* B1p = B1 + ((size_t)(e * NBANDS + band) * RR) * HH + j0 + tx * 4;
        float l0 = 0.f, l1 = 0.f, l2 = 0.f, l3 = 0.f;
#pragma unroll
        for (int r = 0; r < RR; r++) {
            float rv = sR1[p * RR + r];
            float4 bb = *(const float4*)(B1p + (size_t)r * HH);
            l0 += rv * bb.x; l1 += rv * bb.y; l2 += rv * bb.z; l3 += rv * bb.w;
        }
        float4 bias = *(const float4*)(b1 + (size_t)e * HH + j0 + tx * 4);
        float4 hv;
        hv.x = gelu_exact(acc[i][0] + bias.x + SCALING * l0);
        hv.y = gelu_exact(acc[i][1] + bias.y + SCALING * l1);
        hv.z = gelu_exact(acc[i][2] + bias.z + SCALING * l2);
        hv.w = gelu_exact(acc[i][3] + bias.w + SCALING * l3);
        *(float4*)(g_h + (size_t)(row0 + p) * HH + j0 + tx * 4) = hv;
    }
}

// ---------------- s2 = h . A2[e][band] : one warp per pair -------------------
__global__ void k_s2(const float* __restrict__ A2) {
    int p    = blockIdx.x * 4 + (threadIdx.x >> 5);
    int lane = threadIdx.x & 31;
    if (p >= MAXP) return;
    int tok = g_pairTok[p];
    if (tok < 0) {
        if (lane == 0)
            for (int r = 0; r < RR; r++) g_s2[p * RR + r] = 0.f;
        return;
    }
    int e = g_pairExp[p], b = g_pairBand[p];
    const float* A  = A2 + (size_t)(e * NBANDS + b) * HH * RR;
    const float* hr = g_h + (size_t)p * HH;
    float acc[RR];
#pragma unroll
    for (int r = 0; r < RR; r++) acc[r] = 0.f;
    for (int h = lane; h < HH; h += 32) {
        float hv = hr[h];
        const float4* Ar = (const float4*)(A + (size_t)h * RR);
#pragma unroll
        for (int q = 0; q < 4; q++) {
            float4 av = Ar[q];
            acc[q * 4 + 0] += hv * av.x;
            acc[q * 4 + 1] += hv * av.y;
            acc[q * 4 + 2] += hv * av.z;
            acc[q * 4 + 3] += hv * av.w;
        }
    }
#pragma unroll
    for (int r = 0; r < RR; r++)
#pragma unroll
        for (int o = 16; o > 0; o >>= 1) acc[r] += __shfl_xor_sync(0xffffffffu, acc[r], o);
    if (lane == 0)
        for (int r = 0; r < RR; r++) g_s2[p * RR + r] = acc[r];
}

// ---------------- pass 2: y += gate * (h@W2 + b2 + 2*s2@B2) ------------------
__global__ void __launch_bounds__(256) k_mlp2(float* __restrict__ y,
                                              const float* __restrict__ W2,
                                              const float* __restrict__ b2,
                                              const float* __restrict__ B2) {
    __shared__ float As[16 * 68];
    __shared__ float Bs[16 * 64];
    __shared__ int   sTok[64];
    __shared__ int   sBand[64];
    __shared__ float sGate[64];
    __shared__ float sS2[64 * RR];

    int row0 = blockIdx.x * 64;
    if (row0 >= g_offPad[EE]) return;
    int e = 0;
#pragma unroll
    for (int i = 1; i < EE; i++) if (row0 >= g_offPad[i]) e = i;
    int j0  = blockIdx.y * 64;
    int tid = threadIdx.x;

    if (tid < 64) {
        int p = row0 + tid;
        sTok[tid]  = g_pairTok[p];
        sBand[tid] = g_pairBand[p];
        sGate[tid] = g_pairGate[p];
    }
    for (int i = tid; i < 64 * RR; i += 256) sS2[i] = g_s2[(size_t)row0 * RR + i];
    __syncthreads();

    int ty = tid >> 4, tx = tid & 15;
    float acc[4][4];
#pragma unroll
    for (int i = 0; i < 4; i++)
#pragma unroll
        for (int j = 0; j < 4; j++) acc[i][j] = 0.f;

    int pp = tid >> 2;
    int kq = tid & 3;
    const float* hbase = g_h + (size_t)(row0 + pp) * HH + kq * 4;
    const float* Wbase = W2 + (size_t)e * HH * OO + j0;
    int brow = tid >> 4;
    int bcol = (tid & 15) * 4;

    for (int k0 = 0; k0 < HH; k0 += 16) {
        float4 av = *(const float4*)(hbase + k0);
        int kb = kq * 4;
        As[(kb + 0) * 68 + pp] = av.x;
        As[(kb + 1) * 68 + pp] = av.y;
        As[(kb + 2) * 68 + pp] = av.z;
        As[(kb + 3) * 68 + pp] = av.w;
        float4 bv = *(const float4*)(Wbase + (size_t)(k0 + brow) * OO + bcol);
        *(float4*)&Bs[brow * 64 + bcol] = bv;
        __syncthreads();
#pragma unroll
        for (int kk = 0; kk < 16; kk++) {
            float4 a = *(const float4*)&As[kk * 68 + ty * 4];
            float4 b = *(const float4*)&Bs[kk * 64 + tx * 4];
            acc[0][0] += a.x * b.x; acc[0][1] += a.x * b.y; acc[0][2] += a.x * b.z; acc[0][3] += a.x * b.w;
            acc[1][0] += a.y * b.x; acc[1][1] += a.y * b.y; acc[1][2] += a.y * b.z; acc[1][3] += a.y * b.w;
            acc[2][0] += a.z * b.x; acc[2][1] += a.z * b.y; acc[2][2] += a.z * b.z; acc[2][3] += a.z * b.w;
            acc[3][0] += a.w * b.x; acc[3][1] += a.w * b.y; acc[3][2] += a.w * b.z; acc[3][3] += a.w * b.w;
        }
        __syncthreads();
    }

#pragma unroll
    for (int i = 0; i < 4; i++) {
        int p   = ty * 4 + i;
        int tok = sTok[p];
        if (tok < 0) continue;
        int band   = sBand[p];
        float gate = sGate[p];
        const float* B2p = B2 + ((size_t)(e * NBANDS + band) * RR) * OO + j0 + tx * 4;
        float l0 = 0.f, l1 = 0.f, l2 = 0.f, l3 = 0.f;
#pragma unroll
        for (int r = 0; r < RR; r++) {
            float rv = sS2[p * RR + r];
            float4 bb = *(const float4*)(B2p + (size_t)r * OO);
            l0 += rv * bb.x; l1 += rv * bb.y; l2 += rv * bb.z; l3 += rv * bb.w;
        }
        float4 bias = *(const float4*)(b2 + (size_t)e * OO + j0 + tx * 4);
        float v0 = (acc[i][0] + bias.x + SCALING * l0) * gate;
        float v1 = (acc[i][1] + bias.y + SCALING * l1) * gate;
        float v2 = (acc[i][2] + bias.z + SCALING * l2) * gate;
        float v3 = (acc[i][3] + bias.w + SCALING * l3) * gate;
        float* yr = y + (size_t)tok * OO + j0 + tx * 4;
        atomicAdd(yr + 0, v0);
        atomicAdd(yr + 1, v1);
        atomicAdd(yr + 2, v2);
        atomicAdd(yr + 3, v3);
    }
}

// ---------------- launch ------------------------------------------------------
extern "C" void kernel_launch(void* const* d_in, const int* in_sizes, int n_in,
                              void* d_out, int out_size) {
    const float* x    = (const float*)d_in[0];
    const int*   band = (const int*)d_in[1];
    const float* wg   = (const float*)d_in[2];
    const float* W1   = (const float*)d_in[3];
    const float* b1   = (const float*)d_in[4];
    const float* W2   = (const float*)d_in[5];
    const float* b2   = (const float*)d_in[6];
    const float* A1   = (const float*)d_in[7];
    const float* B1   = (const float*)d_in[8];
    const float* A2   = (const float*)d_in[9];
    const float* B2   = (const float*)d_in[10];
    float* out = (float*)d_out;

    k_init<<<(out_size + 255) / 256, 256>>>(out, out_size);
    k_gate<<<NTOK / 4, 128>>>(x, wg);
    k_loss<<<1, 256>>>(out, out_size);
    k_prep<<<(MAXP + 255) / 256, 256>>>();
    k_scatter<<<NTOK / 256, 256>>>(band);
    k_r1<<<MAXP / 4, 128>>>(x, A1);
    {
        dim3 g1(RT_MAX, HH / 64);
        k_mlp1<<<g1, 256>>>(x, W1, b1, B1);
    }
    k_s2<<<MAXP / 4, 128>>>(A2);
    {
        dim3 g2(RT_MAX, OO / 64);
        k_mlp2<<<g2, 256>>>(out, W2, b2, B2);
    }
}

// round 4
// speedup vs baseline: 4.0142x; 4.0142x over previous
#include <cuda_runtime.h>
#include <cuda_bf16.h>
#include <math.h>

typedef __nv_bfloat16 bf16;

#define NTOK 16384
#define DD   1024
#define HH   4096
#define OO   1024
#define EE   8
#define NBANDS 4
#define NG   32            // expert*band groups
#define RR   16
#define MAXP2 36864        // 32768 + 32*128 padding
#define RTMAX2 (MAXP2/128) // 288 row blocks

// ---------------- device scratch ---------------------------------------------
__device__ int   g_e0[NTOK], g_e1[NTOK];
__device__ float g_g0[NTOK], g_g1[NTOK];
__device__ int   g_cntE[EE];
__device__ int   g_cntG[NG];
__device__ int   g_off[NG + 1];
__device__ int   g_cursor[NG];
__device__ int   g_pairTok[MAXP2];
__device__ int   g_pairGrp[MAXP2];
__device__ float g_pairGate[MAXP2];
__device__ bf16  g_r1h[MAXP2 * RR], g_r1l[MAXP2 * RR];
__device__ bf16  g_s2h[MAXP2 * RR], g_s2l[MAXP2 * RR];
__device__ bf16  g_xh[(size_t)NTOK * DD], g_xl[(size_t)NTOK * DD];
__device__ bf16  g_w1h[(size_t)EE * DD * HH], g_w1l[(size_t)EE * DD * HH];
__device__ bf16  g_w2h[(size_t)EE * HH * OO], g_w2l[(size_t)EE * HH * OO];
__device__ bf16  g_b1h[(size_t)NG * RR * HH], g_b1l[(size_t)NG * RR * HH];
__device__ bf16  g_b2h[(size_t)NG * RR * OO], g_b2l[(size_t)NG * RR * OO];
__device__ bf16  g_hh[(size_t)MAXP2 * HH], g_hl[(size_t)MAXP2 * HH];

__device__ __forceinline__ float gelu_exact(float v) {
    return 0.5f * v * (1.0f + erff(v * 0.70710678118654752f));
}
__device__ __forceinline__ void split2(float v, bf16& h, bf16& l) {
    h = __float2bfloat16(v);
    l = __float2bfloat16(v - __bfloat162float(h));
}
__device__ __forceinline__ unsigned sm_u32(const void* p) {
    return (unsigned)__cvta_generic_to_shared(p);
}
__device__ __forceinline__ void cp16(void* d, const void* s, int sz) {
    asm volatile("cp.async.cg.shared.global [%0], [%1], 16, %2;\n"
                 :: "r"(sm_u32(d)), "l"(s), "r"(sz));
}
#define CP_COMMIT asm volatile("cp.async.commit_group;\n")
#define CP_WAIT1  asm volatile("cp.async.wait_group 1;\n")

#define LDSM_X4(R0,R1,R2,R3,ADDR) \
    asm volatile("ldmatrix.sync.aligned.m8n8.x4.shared.b16 {%0,%1,%2,%3}, [%4];\n" \
                 : "=r"(R0),"=r"(R1),"=r"(R2),"=r"(R3) : "r"(ADDR))
#define LDSM_X4T(R0,R1,R2,R3,ADDR) \
    asm volatile("ldmatrix.sync.aligned.m8n8.x4.trans.shared.b16 {%0,%1,%2,%3}, [%4];\n" \
                 : "=r"(R0),"=r"(R1),"=r"(R2),"=r"(R3) : "r"(ADDR))
#define MMA16816(C,A,B) \
    asm volatile("mma.sync.aligned.m16n8k16.row.col.f32.bf16.bf16.f32 " \
                 "{%0,%1,%2,%3},{%4,%5,%6,%7},{%8,%9},{%0,%1,%2,%3};\n" \
                 : "+f"(C[0]),"+f"(C[1]),"+f"(C[2]),"+f"(C[3]) \
                 : "r"(A[0]),"r"(A[1]),"r"(A[2]),"r"(A[3]),"r"(B[0]),"r"(B[1]))

// ---------------- init --------------------------------------------------------
__global__ void k_init(float* __restrict__ y, int out_size) {
    int i = blockIdx.x * 256 + threadIdx.x;
    if (i < out_size) y[i] = 0.f;
    if (i < EE) g_cntE[i] = 0;
    if (i < NG) g_cntG[i] = 0;
}

// ---------------- gating ------------------------------------------------------
__global__ void k_gate(const float* __restrict__ x, const float* __restrict__ wg,
                       const int* __restrict__ band) {
    int tok  = blockIdx.x * 4 + (threadIdx.x >> 5);
    int lane = threadIdx.x & 31;
    if (tok >= NTOK) return;
    const float* xr = x + (size_t)tok * DD;
    float acc[EE];
#pragma unroll
    for (int e = 0; e < EE; e++) acc[e] = 0.f;
    for (int d = lane; d < DD; d += 32) {
        float xv = xr[d];
        const float* w = wg + d * EE;
#pragma unroll
        for (int e = 0; e < EE; e++) acc[e] += xv * w[e];
    }
#pragma unroll
    for (int e = 0; e < EE; e++)
#pragma unroll
        for (int o = 16; o > 0; o >>= 1) acc[e] += __shfl_xor_sync(0xffffffffu, acc[e], o);
    if (lane == 0) {
        int e0 = 0; float v0 = acc[0];
#pragma unroll
        for (int e = 1; e < EE; e++) if (acc[e] > v0) { v0 = acc[e]; e0 = e; }
        int e1 = -1; float v1 = -INFINITY;
#pragma unroll
        for (int e = 0; e < EE; e++) if (e != e0 && acc[e] > v1) { v1 = acc[e]; e1 = e; }
        float z1 = expf(v1 - v0);
        float den = 1.0f + z1;
        g_e0[tok] = e0; g_e1[tok] = e1;
        g_g0[tok] = 1.0f / den; g_g1[tok] = z1 / den;
        int b = band[tok];
        atomicAdd(&g_cntE[e0], 1); atomicAdd(&g_cntE[e1], 1);
        atomicAdd(&g_cntG[e0 * NBANDS + b], 1);
        atomicAdd(&g_cntG[e1 * NBANDS + b], 1);
    }
}

// ---------------- loss --------------------------------------------------------
__global__ void k_loss(float* __restrict__ out, int out_size) {
    __shared__ float s[EE * 256];
    float acc[EE];
#pragma unroll
    for (int e = 0; e < EE; e++) acc[e] = 0.f;
    for (int t = threadIdx.x; t < NTOK; t += 256) {
        int e0 = g_e0[t], e1 = g_e1[t];
        float g0 = g_g0[t], g1 = g_g1[t];
#pragma unroll
        for (int e = 0; e < EE; e++)
            acc[e] += (e == e0 ? g0 : 0.f) + (e == e1 ? g1 : 0.f);
    }
#pragma unroll
    for (int e = 0; e < EE; e++) s[e * 256 + threadIdx.x] = acc[e];
    __syncthreads();
    for (int st = 128; st > 0; st >>= 1) {
        if (threadIdx.x < st)
#pragma unroll
            for (int e = 0; e < EE; e++)
                s[e * 256 + threadIdx.x] += s[e * 256 + threadIdx.x + st];
        __syncthreads();
    }
    if (threadIdx.x == 0) {
        float imp[EE], ld[EE];
#pragma unroll
        for (int e = 0; e < EE; e++) { imp[e] = s[e * 256]; ld[e] = (float)g_cntE[e]; }
        float m1 = 0.f, m2 = 0.f;
#pragma unroll
        for (int e = 0; e < EE; e++) { m1 += imp[e]; m2 += ld[e]; }
        m1 /= EE; m2 /= EE;
        float v1 = 0.f, v2 = 0.f;
#pragma unroll
        for (int e = 0; e < EE; e++) {
            float d1 = imp[e] - m1, d2 = ld[e] - m2;
            v1 += d1 * d1; v2 += d2 * d2;
        }
        v1 /= (EE - 1); v2 /= (EE - 1);
        out[out_size - 1] = 0.01f * (v1 / (m1 * m1 + 1e-10f) + v2 / (m2 * m2 + 1e-10f));
    }
}

// ---------------- prep + scatter ---------------------------------------------
__global__ void k_prep() {
    int i = blockIdx.x * 256 + threadIdx.x;
    if (i < MAXP2) { g_pairTok[i] = -1; g_pairGrp[i] = 0; g_pairGate[i] = 0.f; }
    if (i == 0) {
        int off = 0;
        for (int g = 0; g < NG; g++) {
            g_off[g] = off; g_cursor[g] = off;
            off += ((g_cntG[g] + 127) >> 7) << 7;
        }
        g_off[NG] = off;
    }
}

__global__ void k_scatter(const int* __restrict__ band) {
    int t = blockIdx.x * 256 + threadIdx.x;
    if (t >= NTOK) return;
    int b = band[t];
    int grp0 = g_e0[t] * NBANDS + b;
    int p0 = atomicAdd(&g_cursor[grp0], 1);
    g_pairTok[p0] = t; g_pairGrp[p0] = grp0; g_pairGate[p0] = g_g0[t];
    int grp1 = g_e1[t] * NBANDS + b;
    int p1 = atomicAdd(&g_cursor[grp1], 1);
    g_pairTok[p1] = t; g_pairGrp[p1] = grp1; g_pairGate[p1] = g_g1[t];
}

// ---------------- fp32 -> bf16 hi/lo split kernels ---------------------------
__device__ __forceinline__ void split_body(const float* __restrict__ src,
                                           bf16* __restrict__ hi, bf16* __restrict__ lo,
                                           int n4) {
    int i = blockIdx.x * 256 + threadIdx.x;
    if (i >= n4) return;
    float4 v = ((const float4*)src)[i];
    bf16 h0, h1, h2, h3, l0, l1, l2, l3;
    split2(v.x, h0, l0); split2(v.y, h1, l1);
    split2(v.z, h2, l2); split2(v.w, h3, l3);
    ((__nv_bfloat162*)hi)[i * 2 + 0] = __halves2bfloat162(h0, h1);
    ((__nv_bfloat162*)hi)[i * 2 + 1] = __halves2bfloat162(h2, h3);
    ((__nv_bfloat162*)lo)[i * 2 + 0] = __halves2bfloat162(l0, l1);
    ((__nv_bfloat162*)lo)[i * 2 + 1] = __halves2bfloat162(l2, l3);
}
__global__ void k_split_x (const float* s) { split_body(s, g_xh,  g_xl,  NTOK * DD / 4); }
__global__ void k_split_w1(const float* s) { split_body(s, g_w1h, g_w1l, EE * DD * HH / 4); }
__global__ void k_split_w2(const float* s) { split_body(s, g_w2h, g_w2l, EE * HH * OO / 4); }
__global__ void k_split_b1(const float* s) { split_body(s, g_b1h, g_b1l, NG * RR * HH / 4); }
__global__ void k_split_b2(const float* s) { split_body(s, g_b2h, g_b2l, NG * RR * OO / 4); }

// ---------------- r1 = 2*(x . A1[grp]) : warp per pair, split-stored ---------
__global__ void k_r1(const float* __restrict__ x, const float* __restrict__ A1) {
    int p    = blockIdx.x * 4 + (threadIdx.x >> 5);
    int lane = threadIdx.x & 31;
    if (p >= MAXP2) return;
    int tok = g_pairTok[p];
    if (tok < 0) {
        if (lane == 0)
            for (int r = 0; r < RR; r++) { g_r1h[p * RR + r] = __float2bfloat16(0.f); g_r1l[p * RR + r] = __float2bfloat16(0.f); }
        return;
    }
    int grp = g_pairGrp[p];
    const float* A  = A1 + (size_t)grp * DD * RR;
    const float* xr = x + (size_t)tok * DD;
    float acc[RR];
#pragma unroll
    for (int r = 0; r < RR; r++) acc[r] = 0.f;
    for (int d = lane; d < DD; d += 32) {
        float xv = xr[d];
        const float4* Ar = (const float4*)(A + (size_t)d * RR);
#pragma unroll
        for (int q = 0; q < 4; q++) {
            float4 av = Ar[q];
            acc[q * 4 + 0] += xv * av.x; acc[q * 4 + 1] += xv * av.y;
            acc[q * 4 + 2] += xv * av.z; acc[q * 4 + 3] += xv * av.w;
        }
    }
#pragma unroll
    for (int r = 0; r < RR; r++)
#pragma unroll
        for (int o = 16; o > 0; o >>= 1) acc[r] += __shfl_xor_sync(0xffffffffu, acc[r], o);
    if (lane == 0)
        for (int r = 0; r < RR; r++) {
            bf16 h, l; split2(2.0f * acc[r], h, l);
            g_r1h[p * RR + r] = h; g_r1l[p * RR + r] = l;
        }
}

// ---------------- s2 = 2*(h . A2[grp]) ---------------------------------------
__global__ void k_s2(const float* __restrict__ A2) {
    int p    = blockIdx.x * 4 + (threadIdx.x >> 5);
    int lane = threadIdx.x & 31;
    if (p >= MAXP2) return;
    int tok = g_pairTok[p];
    if (tok < 0) {
        if (lane == 0)
            for (int r = 0; r < RR; r++) { g_s2h[p * RR + r] = __float2bfloat16(0.f); g_s2l[p * RR + r] = __float2bfloat16(0.f); }
        return;
    }
    int grp = g_pairGrp[p];
    const float* A = A2 + (size_t)grp * HH * RR;
    const bf16* hh = g_hh + (size_t)p * HH;
    const bf16* hl = g_hl + (size_t)p * HH;
    float acc[RR];
#pragma unroll
    for (int r = 0; r < RR; r++) acc[r] = 0.f;
    for (int h = lane; h < HH; h += 32) {
        float hv = __bfloat162float(hh[h]) + __bfloat162float(hl[h]);
        const float4* Ar = (const float4*)(A + (size_t)h * RR);
#pragma unroll
        for (int q = 0; q < 4; q++) {
            float4 av = Ar[q];
            acc[q * 4 + 0] += hv * av.x; acc[q * 4 + 1] += hv * av.y;
            acc[q * 4 + 2] += hv * av.z; acc[q * 4 + 3] += hv * av.w;
        }
    }
#pragma unroll
    for (int r = 0; r < RR; r++)
#pragma unroll
        for (int o = 16; o > 0; o >>= 1) acc[r] += __shfl_xor_sync(0xffffffffu, acc[r], o);
    if (lane == 0)
        for (int r = 0; r < RR; r++) {
            bf16 h, l; split2(2.0f * acc[r], h, l);
            g_s2h[p * RR + r] = h; g_s2l[p * RR + r] = l;
        }
}

// ---------------- tensor-core GEMM (split bf16, 3-term) ----------------------
// MLP1: h_split = gelu(x@W1 + b1 + r1s@B1);  MLP2: y += gate*(h@W2 + b2 + s2s@B2)
template<int KD, int ND, bool MLP1>
__global__ void __launch_bounds__(256) k_gemm(const float* __restrict__ bias_g,
                                              float* __restrict__ y) {
    __shared__ bf16 Ah[2][128][24], Al[2][128][24];
    __shared__ bf16 Bh[2][16][136], Bl[2][16][136];
    __shared__ int   sTok[128];
    __shared__ float sGate[128];

    int row0 = blockIdx.x * 128;
    if (row0 >= g_off[NG]) return;
    int grp = 0;
#pragma unroll
    for (int i = 1; i < NG; i++) if (row0 >= g_off[i]) grp = i;
    int e  = grp >> 2;
    int j0 = blockIdx.y * 128;
    int tid = threadIdx.x;

    if (tid < 128) {
        sTok[tid]  = g_pairTok[row0 + tid];
        sGate[tid] = g_pairGate[row0 + tid];
    }
    __syncthreads();

    const int aR = tid >> 1, aH = tid & 1;      // A fill: 128 rows x 2 halves
    const int bR = tid >> 4, bS = tid & 15;     // B fill: 16 rows x 16 segs
    const int SM = KD / 16;
    const int S  = SM + 1;                      // + LoRA stage

    auto fill = [&](int s, int buf) {
        if (s < SM) {
            int k0 = s * 16;
            size_t aoff; int sz = 16;
            if (MLP1) {
                int tok = sTok[aR];
                sz = tok >= 0 ? 16 : 0;
                aoff = (size_t)(tok >= 0 ? tok : 0) * KD + k0 + aH * 8;
            } else {
                aoff = (size_t)(row0 + aR) * KD + k0 + aH * 8;
            }
            cp16(&Ah[buf][aR][aH * 8], (MLP1 ? g_xh : g_hh) + aoff, sz);
            cp16(&Al[buf][aR][aH * 8], (MLP1 ? g_xl : g_hl) + aoff, sz);
            size_t woff = (size_t)e * ((size_t)KD * ND) + (size_t)(k0 + bR) * ND + j0 + bS * 8;
            cp16(&Bh[buf][bR][bS * 8], (MLP1 ? g_w1h : g_w2h) + woff, 16);
            cp16(&Bl[buf][bR][bS * 8], (MLP1 ? g_w1l : g_w2l) + woff, 16);
        } else {
            // LoRA stage: A=[r1h / r1l], B=[B1h / B1l]; 3-term gives r1*B1h + r1h*B1l
            size_t roff = (size_t)(row0 + aR) * RR + aH * 8;
            cp16(&Ah[buf][aR][aH * 8], (MLP1 ? g_r1h : g_s2h) + roff, 16);
            cp16(&Al[buf][aR][aH * 8], (MLP1 ? g_r1l : g_s2l) + roff, 16);
            size_t boff = ((size_t)grp * RR + bR) * ND + j0 + bS * 8;
            cp16(&Bh[buf][bR][bS * 8], (MLP1 ? g_b1h : g_b2h) + boff, 16);
            cp16(&Bl[buf][bR][bS * 8], (MLP1 ? g_b1l : g_b2l) + boff, 16);
        }
        CP_COMMIT;
    };

    const int warp = tid >> 5, lane = tid & 31;
    const int wm = (warp >> 2) * 64, wn = (warp & 3) * 32;

    float acc[4][4][4];
#pragma unroll
    for (int mt = 0; mt < 4; mt++)
#pragma unroll
        for (int nt = 0; nt < 4; nt++)
#pragma unroll
            for (int q = 0; q < 4; q++) acc[mt][nt][q] = 0.f;

    fill(0, 0);
    const int arow = lane & 15, acol = (lane >> 4) * 8;
    const int bg = lane >> 3;
    const int brow = (bg & 1) * 8 + (lane & 7);

    for (int s = 0; s < S; s++) {
        if (s + 1 < S) fill(s + 1, (s + 1) & 1); else CP_COMMIT;
        CP_WAIT1;
        __syncthreads();
        int buf = s & 1;

        unsigned ah[4][4], al[4][4], bh[4][2], bl[4][2];
#pragma unroll
        for (int mt = 0; mt < 4; mt++) {
            unsigned ad = sm_u32(&Ah[buf][wm + mt * 16 + arow][acol]);
            LDSM_X4(ah[mt][0], ah[mt][1], ah[mt][2], ah[mt][3], ad);
            unsigned ad2 = sm_u32(&Al[buf][wm + mt * 16 + arow][acol]);
            LDSM_X4(al[mt][0], al[mt][1], al[mt][2], al[mt][3], ad2);
        }
#pragma unroll
        for (int np = 0; np < 2; np++) {
            int bcol = wn + (np * 2 + (bg >> 1)) * 8;
            unsigned bd = sm_u32(&Bh[buf][brow][bcol]);
            LDSM_X4T(bh[np * 2][0], bh[np * 2][1], bh[np * 2 + 1][0], bh[np * 2 + 1][1], bd);
            unsigned bd2 = sm_u32(&Bl[buf][brow][bcol]);
            LDSM_X4T(bl[np * 2][0], bl[np * 2][1], bl[np * 2 + 1][0], bl[np * 2 + 1][1], bd2);
        }
#pragma unroll
        for (int mt = 0; mt < 4; mt++)
#pragma unroll
            for (int nt = 0; nt < 4; nt++) MMA16816(acc[mt][nt], ah[mt], bh[nt]);
#pragma unroll
        for (int mt = 0; mt < 4; mt++)
#pragma unroll
            for (int nt = 0; nt < 4; nt++) MMA16816(acc[mt][nt], ah[mt], bl[nt]);
#pragma unroll
        for (int mt = 0; mt < 4; mt++)
#pragma unroll
            for (int nt = 0; nt < 4; nt++) MMA16816(acc[mt][nt], al[mt], bh[nt]);
        __syncthreads();
    }

    // epilogue
#pragma unroll
    for (int mt = 0; mt < 4; mt++) {
#pragma unroll
        for (int nt = 0; nt < 4; nt++) {
            int c0  = wn + nt * 8 + (lane & 3) * 2;
            int col = j0 + c0;
            float bias0 = bias_g[(size_t)e * ND + col];
            float bias1 = bias_g[(size_t)e * ND + col + 1];
#pragma unroll
            for (int hf = 0; hf < 2; hf++) {
                int r = wm + mt * 16 + (lane >> 2) + hf * 8;
                float v0 = acc[mt][nt][hf * 2 + 0] + bias0;
                float v1 = acc[mt][nt][hf * 2 + 1] + bias1;
                if (MLP1) {
                    v0 = gelu_exact(v0); v1 = gelu_exact(v1);
                    bf16 h0, l0, h1, l1;
                    split2(v0, h0, l0); split2(v1, h1, l1);
                    size_t o = (size_t)(row0 + r) * ND + col;
                    *(__nv_bfloat162*)(g_hh + o) = __halves2bfloat162(h0, h1);
                    *(__nv_bfloat162*)(g_hl + o) = __halves2bfloat162(l0, l1);
                } else {
                    int tok = sTok[r];
                    if (tok >= 0) {
                        float gv = sGate[r];
                        atomicAdd(y + (size_t)tok * ND + col,     gv * v0);
                        atomicAdd(y + (size_t)tok * ND + col + 1, gv * v1);
                    }
                }
            }
        }
    }
}

// ---------------- launch ------------------------------------------------------
extern "C" void kernel_launch(void* const* d_in, const int* in_sizes, int n_in,
                              void* d_out, int out_size) {
    const float* x    = (const float*)d_in[0];
    const int*   band = (const int*)d_in[1];
    const float* wg   = (const float*)d_in[2];
    const float* W1   = (const float*)d_in[3];
    const float* b1   = (const float*)d_in[4];
    const float* W2   = (const float*)d_in[5];
    const float* b2   = (const float*)d_in[6];
    const float* A1   = (const float*)d_in[7];
    const float* B1   = (const float*)d_in[8];
    const float* A2   = (const float*)d_in[9];
    const float* B2   = (const float*)d_in[10];
    float* out = (float*)d_out;

    k_init<<<(out_size + 255) / 256, 256>>>(out, out_size);
    k_gate<<<NTOK / 4, 128>>>(x, wg, band);
    k_loss<<<1, 256>>>(out, out_size);
    k_prep<<<(MAXP2 + 255) / 256, 256>>>();
    k_scatter<<<NTOK / 256, 256>>>(band);

    k_split_x <<<(NTOK * DD / 4 + 255) / 256, 256>>>(x);
    k_split_w1<<<(EE * DD * HH / 4 + 255) / 256, 256>>>(W1);
    k_split_w2<<<(EE * HH * OO / 4 + 255) / 256, 256>>>(W2);
    k_split_b1<<<(NG * RR * HH / 4 + 255) / 256, 256>>>(B1);
    k_split_b2<<<(NG * RR * OO / 4 + 255) / 256, 256>>>(B2);

    k_r1<<<MAXP2 / 4, 128>>>(x, A1);
    k_gemm<DD, HH, true ><<<dim3(RTMAX2, HH / 128), 256>>>(b1, nullptr);
    k_s2<<<MAXP2 / 4, 128>>>(A2);
    k_gemm<HH, OO, false><<<dim3(RTMAX2, OO / 128), 256>>>(b2, out);
}

// round 9
// speedup vs baseline: 4.2675x; 1.0631x over previous
#include <cuda_runtime.h>
#include <cuda_bf16.h>
#include <math.h>

typedef __nv_bfloat16 bf16;

#define NTOK 16384
#define DD   1024
#define HH   4096
#define OO   1024
#define EE   8
#define NBANDS 4
#define NG   32            // expert*band groups
#define RR   16
#define MAXP2 36864        // 32768 + 32*128 padding
#define RTMAX2 (MAXP2/128) // 288 row blocks

// ---------------- device scratch ---------------------------------------------
__device__ int   g_e0[NTOK], g_e1[NTOK];
__device__ float g_g0[NTOK], g_g1[NTOK];
__device__ int   g_cntE[EE];
__device__ int   g_cntG[NG];
__device__ int   g_off[NG + 1];
__device__ int   g_cursor[NG];
__device__ int   g_pairTok[MAXP2];
__device__ int   g_pairGrp[MAXP2];
__device__ float g_pairGate[MAXP2];
__device__ bf16  g_r1h[MAXP2 * RR], g_r1l[MAXP2 * RR];
__device__ bf16  g_s2h[MAXP2 * RR], g_s2l[MAXP2 * RR];
__device__ bf16  g_xh[(size_t)NTOK * DD], g_xl[(size_t)NTOK * DD];
__device__ bf16  g_w1h[(size_t)EE * DD * HH], g_w1l[(size_t)EE * DD * HH];
__device__ bf16  g_w2h[(size_t)EE * HH * OO], g_w2l[(size_t)EE * HH * OO];
__device__ bf16  g_b1h[(size_t)NG * RR * HH], g_b1l[(size_t)NG * RR * HH];
__device__ bf16  g_b2h[(size_t)NG * RR * OO], g_b2l[(size_t)NG * RR * OO];
__device__ bf16  g_hh[(size_t)MAXP2 * HH], g_hl[(size_t)MAXP2 * HH];

__device__ __forceinline__ float gelu_exact(float v) {
    return 0.5f * v * (1.0f + erff(v * 0.70710678118654752f));
}
__device__ __forceinline__ void split2(float v, bf16& h, bf16& l) {
    h = __float2bfloat16(v);
    l = __float2bfloat16(v - __bfloat162float(h));
}
__device__ __forceinline__ unsigned sm_u32(const void* p) {
    return (unsigned)__cvta_generic_to_shared(p);
}
__device__ __forceinline__ void cp16(void* d, const void* s, int sz) {
    asm volatile("cp.async.cg.shared.global [%0], [%1], 16, %2;\n"
                 :: "r"(sm_u32(d)), "l"(s), "r"(sz));
}
#define CP_COMMIT asm volatile("cp.async.commit_group;\n")
#define CP_WAIT1  asm volatile("cp.async.wait_group 1;\n")

#define LDSM_X4(R0,R1,R2,R3,ADDR) \
    asm volatile("ldmatrix.sync.aligned.m8n8.x4.shared.b16 {%0,%1,%2,%3}, [%4];\n" \
                 : "=r"(R0),"=r"(R1),"=r"(R2),"=r"(R3) : "r"(ADDR))
#define LDSM_X4T(R0,R1,R2,R3,ADDR) \
    asm volatile("ldmatrix.sync.aligned.m8n8.x4.trans.shared.b16 {%0,%1,%2,%3}, [%4];\n" \
                 : "=r"(R0),"=r"(R1),"=r"(R2),"=r"(R3) : "r"(ADDR))
#define MMA16816(C,A,B) \
    asm volatile("mma.sync.aligned.m16n8k16.row.col.f32.bf16.bf16.f32 " \
                 "{%0,%1,%2,%3},{%4,%5,%6,%7},{%8,%9},{%0,%1,%2,%3};\n" \
                 : "+f"(C[0]),"+f"(C[1]),"+f"(C[2]),"+f"(C[3]) \
                 : "r"(A[0]),"r"(A[1]),"r"(A[2]),"r"(A[3]),"r"(B[0]),"r"(B[1]))

// ---------------- init --------------------------------------------------------
__global__ void k_init(float* __restrict__ y, int out_size) {
    int i = blockIdx.x * 256 + threadIdx.x;
    if (i < out_size) y[i] = 0.f;
    if (i < EE) g_cntE[i] = 0;
    if (i < NG) g_cntG[i] = 0;
}

// ---------------- gating ------------------------------------------------------
__global__ void k_gate(const float* __restrict__ x, const float* __restrict__ wg,
                       const int* __restrict__ band) {
    int tok  = blockIdx.x * 4 + (threadIdx.x >> 5);
    int lane = threadIdx.x & 31;
    if (tok >= NTOK) return;
    const float* xr = x + (size_t)tok * DD;
    float acc[EE];
#pragma unroll
    for (int e = 0; e < EE; e++) acc[e] = 0.f;
    for (int d = lane; d < DD; d += 32) {
        float xv = xr[d];
        const float* w = wg + d * EE;
#pragma unroll
        for (int e = 0; e < EE; e++) acc[e] += xv * w[e];
    }
#pragma unroll
    for (int e = 0; e < EE; e++)
#pragma unroll
        for (int o = 16; o > 0; o >>= 1) acc[e] += __shfl_xor_sync(0xffffffffu, acc[e], o);
    if (lane == 0) {
        int e0 = 0; float v0 = acc[0];
#pragma unroll
        for (int e = 1; e < EE; e++) if (acc[e] > v0) { v0 = acc[e]; e0 = e; }
        int e1 = -1; float v1 = -INFINITY;
#pragma unroll
        for (int e = 0; e < EE; e++) if (e != e0 && acc[e] > v1) { v1 = acc[e]; e1 = e; }
        float z1 = expf(v1 - v0);
        float den = 1.0f + z1;
        g_e0[tok] = e0; g_e1[tok] = e1;
        g_g0[tok] = 1.0f / den; g_g1[tok] = z1 / den;
        int b = band[tok];
        atomicAdd(&g_cntE[e0], 1); atomicAdd(&g_cntE[e1], 1);
        atomicAdd(&g_cntG[e0 * NBANDS + b], 1);
        atomicAdd(&g_cntG[e1 * NBANDS + b], 1);
    }
}

// ---------------- loss --------------------------------------------------------
__global__ void k_loss(float* __restrict__ out, int out_size) {
    __shared__ float s[EE * 256];
    float acc[EE];
#pragma unroll
    for (int e = 0; e < EE; e++) acc[e] = 0.f;
    for (int t = threadIdx.x; t < NTOK; t += 256) {
        int e0 = g_e0[t], e1 = g_e1[t];
        float g0 = g_g0[t], g1 = g_g1[t];
#pragma unroll
        for (int e = 0; e < EE; e++)
            acc[e] += (e == e0 ? g0 : 0.f) + (e == e1 ? g1 : 0.f);
    }
#pragma unroll
    for (int e = 0; e < EE; e++) s[e * 256 + threadIdx.x] = acc[e];
    __syncthreads();
    for (int st = 128; st > 0; st >>= 1) {
        if (threadIdx.x < st)
#pragma unroll
            for (int e = 0; e < EE; e++)
                s[e * 256 + threadIdx.x] += s[e * 256 + threadIdx.x + st];
        __syncthreads();
    }
    if (threadIdx.x == 0) {
        float imp[EE], ld[EE];
#pragma unroll
        for (int e = 0; e < EE; e++) { imp[e] = s[e * 256]; ld[e] = (float)g_cntE[e]; }
        float m1 = 0.f, m2 = 0.f;
#pragma unroll
        for (int e = 0; e < EE; e++) { m1 += imp[e]; m2 += ld[e]; }
        m1 /= EE; m2 /= EE;
        float v1 = 0.f, v2 = 0.f;
#pragma unroll
        for (int e = 0; e < EE; e++) {
            float d1 = imp[e] - m1, d2 = ld[e] - m2;
            v1 += d1 * d1; v2 += d2 * d2;
        }
        v1 /= (EE - 1); v2 /= (EE - 1);
        out[out_size - 1] = 0.01f * (v1 / (m1 * m1 + 1e-10f) + v2 / (m2 * m2 + 1e-10f));
    }
}

// ---------------- prep + scatter ---------------------------------------------
__global__ void k_prep() {
    int i = blockIdx.x * 256 + threadIdx.x;
    if (i < MAXP2) { g_pairTok[i] = -1; g_pairGrp[i] = 0; g_pairGate[i] = 0.f; }
    if (i == 0) {
        int off = 0;
        for (int g = 0; g < NG; g++) {
            g_off[g] = off; g_cursor[g] = off;
            off += ((g_cntG[g] + 127) >> 7) << 7;
        }
        g_off[NG] = off;
    }
}

__global__ void k_scatter(const int* __restrict__ band) {
    int t = blockIdx.x * 256 + threadIdx.x;
    if (t >= NTOK) return;
    int b = band[t];
    int grp0 = g_e0[t] * NBANDS + b;
    int p0 = atomicAdd(&g_cursor[grp0], 1);
    g_pairTok[p0] = t; g_pairGrp[p0] = grp0; g_pairGate[p0] = g_g0[t];
    int grp1 = g_e1[t] * NBANDS + b;
    int p1 = atomicAdd(&g_cursor[grp1], 1);
    g_pairTok[p1] = t; g_pairGrp[p1] = grp1; g_pairGate[p1] = g_g1[t];
}

// ---------------- fp32 -> bf16 hi/lo split kernels ---------------------------
__device__ __forceinline__ void split_body(const float* __restrict__ src,
                                           bf16* __restrict__ hi, bf16* __restrict__ lo,
                                           int n4) {
    int i = blockIdx.x * 256 + threadIdx.x;
    if (i >= n4) return;
    float4 v = ((const float4*)src)[i];
    bf16 h0, h1, h2, h3, l0, l1, l2, l3;
    split2(v.x, h0, l0); split2(v.y, h1, l1);
    split2(v.z, h2, l2); split2(v.w, h3, l3);
    ((__nv_bfloat162*)hi)[i * 2 + 0] = __halves2bfloat162(h0, h1);
    ((__nv_bfloat162*)hi)[i * 2 + 1] = __halves2bfloat162(h2, h3);
    ((__nv_bfloat162*)lo)[i * 2 + 0] = __halves2bfloat162(l0, l1);
    ((__nv_bfloat162*)lo)[i * 2 + 1] = __halves2bfloat162(l2, l3);
}
__global__ void k_split_x (const float* s) { split_body(s, g_xh,  g_xl,  NTOK * DD / 4); }
__global__ void k_split_w1(const float* s) { split_body(s, g_w1h, g_w1l, EE * DD * HH / 4); }
__global__ void k_split_w2(const float* s) { split_body(s, g_w2h, g_w2l, EE * HH * OO / 4); }
__global__ void k_split_b1(const float* s) { split_body(s, g_b1h, g_b1l, NG * RR * HH / 4); }
__global__ void k_split_b2(const float* s) { split_body(s, g_b2h, g_b2l, NG * RR * OO / 4); }

// ---------------- group id for a row block (shared helper) -------------------
__device__ __forceinline__ int grp_of(int row0) {
    int grp = 0;
#pragma unroll
    for (int i = 1; i < NG; i++) if (row0 >= g_off[i]) grp = i;
    return grp;
}

// ---------------- r1 = 2*(x . A1[grp]) : block-cooperative, smem A ----------
__global__ void __launch_bounds__(256) k_r1(const float* __restrict__ x,
                                            const float* __restrict__ A1) {
    __shared__ float sA[32][RR];
    int row0 = blockIdx.x * 128;
    int grp  = grp_of(row0);
    int tid  = threadIdx.x;
    int row  = tid >> 1;          // 0..127
    int half = tid & 1;           // r in [half*8, half*8+8)
    int tok  = g_pairTok[row0 + row];
    const float* A = A1 + (size_t)grp * DD * RR;

    float acc[8];
#pragma unroll
    for (int q = 0; q < 8; q++) acc[q] = 0.f;

    for (int k0 = 0; k0 < DD; k0 += 32) {
        int kk = tid >> 3, rp = tid & 7;
        *(float2*)&sA[kk][rp * 2] = *(const float2*)(A + (size_t)(k0 + kk) * RR + rp * 2);
        __syncthreads();
        if (tok >= 0) {
            const float* xr = x + (size_t)tok * DD + k0;
#pragma unroll
            for (int k = 0; k < 32; k++) {
                float xv = xr[k];
                float4 a0 = *(const float4*)&sA[k][half * 8];
                float4 a1 = *(const float4*)&sA[k][half * 8 + 4];
                acc[0] += xv * a0.x; acc[1] += xv * a0.y;
                acc[2] += xv * a0.z; acc[3] += xv * a0.w;
                acc[4] += xv * a1.x; acc[5] += xv * a1.y;
                acc[6] += xv * a1.z; acc[7] += xv * a1.w;
            }
        }
        __syncthreads();
    }
#pragma unroll
    for (int q = 0; q < 8; q++) {
        bf16 h, l; split2(2.0f * acc[q], h, l);
        size_t o = (size_t)(row0 + row) * RR + half * 8 + q;
        g_r1h[o] = h; g_r1l[o] = l;
    }
}

// ---------------- s2 = 2*(h . A2[grp]) : block-cooperative, smem A -----------
__global__ void __launch_bounds__(256) k_s2(const float* __restrict__ A2) {
    __shared__ float sA[32][RR];
    int row0 = blockIdx.x * 128;
    int grp  = grp_of(row0);
    int tid  = threadIdx.x;
    int row  = tid >> 1;
    int half = tid & 1;
    const float* A = A2 + (size_t)grp * HH * RR;
    const __nv_bfloat162* hh = (const __nv_bfloat162*)(g_hh + (size_t)(row0 + row) * HH);
    const __nv_bfloat162* hl = (const __nv_bfloat162*)(g_hl + (size_t)(row0 + row) * HH);

    float acc[8];
#pragma unroll
    for (int q = 0; q < 8; q++) acc[q] = 0.f;

    for (int k0 = 0; k0 < HH; k0 += 32) {
        int kk = tid >> 3, rp = tid & 7;
        *(float2*)&sA[kk][rp * 2] = *(const float2*)(A + (size_t)(k0 + kk) * RR + rp * 2);
        __syncthreads();
#pragma unroll
        for (int k2 = 0; k2 < 16; k2++) {
            __nv_bfloat162 vh = hh[k0 / 2 + k2];
            __nv_bfloat162 vl = hl[k0 / 2 + k2];
            float hv0 = __bfloat162float(vh.x) + __bfloat162float(vl.x);
            float hv1 = __bfloat162float(vh.y) + __bfloat162float(vl.y);
#pragma unroll
            for (int pair = 0; pair < 2; pair++) {
                float xv = pair ? hv1 : hv0;
                int k = k2 * 2 + pair;
                float4 a0 = *(const float4*)&sA[k][half * 8];
                float4 a1 = *(const float4*)&sA[k][half * 8 + 4];
                acc[0] += xv * a0.x; acc[1] += xv * a0.y;
                acc[2] += xv * a0.z; acc[3] += xv * a0.w;
                acc[4] += xv * a1.x; acc[5] += xv * a1.y;
                acc[6] += xv * a1.z; acc[7] += xv * a1.w;
            }
        }
        __syncthreads();
    }
#pragma unroll
    for (int q = 0; q < 8; q++) {
        bf16 h, l; split2(2.0f * acc[q], h, l);
        size_t o = (size_t)(row0 + row) * RR + half * 8 + q;
        g_s2h[o] = h; g_s2l[o] = l;
    }
}

// ---------------- tensor-core GEMM (split bf16, 3-term) ----------------------
// Grid: x = column tiles (fast) so same-A CTAs are schedule-adjacent.
template<int KD, int ND, bool MLP1>
__global__ void __launch_bounds__(256) k_gemm(const float* __restrict__ bias_g,
                                              float* __restrict__ y) {
    __shared__ bf16 Ah[2][128][24], Al[2][128][24];
    __shared__ bf16 Bh[2][16][136], Bl[2][16][136];
    __shared__ int   sTok[128];
    __shared__ float sGate[128];

    int row0 = blockIdx.y * 128;
    if (row0 >= g_off[NG]) return;
    int grp = grp_of(row0);
    int e  = grp >> 2;
    int j0 = blockIdx.x * 128;
    int tid = threadIdx.x;

    if (tid < 128) {
        sTok[tid]  = g_pairTok[row0 + tid];
        sGate[tid] = g_pairGate[row0 + tid];
    }
    __syncthreads();

    const int aR = tid >> 1, aH = tid & 1;      // A fill: 128 rows x 2 halves
    const int bR = tid >> 4, bS = tid & 15;     // B fill: 16 rows x 16 segs
    const int SM = KD / 16;
    const int S  = SM + 1;                      // + LoRA stage

    auto fill = [&](int s, int buf) {
        if (s < SM) {
            int k0 = s * 16;
            size_t aoff; int sz = 16;
            if (MLP1) {
                int tok = sTok[aR];
                sz = tok >= 0 ? 16 : 0;
                aoff = (size_t)(tok >= 0 ? tok : 0) * KD + k0 + aH * 8;
            } else {
                aoff = (size_t)(row0 + aR) * KD + k0 + aH * 8;
            }
            cp16(&Ah[buf][aR][aH * 8], (MLP1 ? g_xh : g_hh) + aoff, sz);
            cp16(&Al[buf][aR][aH * 8], (MLP1 ? g_xl : g_hl) + aoff, sz);
            size_t woff = (size_t)e * ((size_t)KD * ND) + (size_t)(k0 + bR) * ND + j0 + bS * 8;
            cp16(&Bh[buf][bR][bS * 8], (MLP1 ? g_w1h : g_w2h) + woff, 16);
            cp16(&Bl[buf][bR][bS * 8], (MLP1 ? g_w1l : g_w2l) + woff, 16);
        } else {
            size_t roff = (size_t)(row0 + aR) * RR + aH * 8;
            cp16(&Ah[buf][aR][aH * 8], (MLP1 ? g_r1h : g_s2h) + roff, 16);
            cp16(&Al[buf][aR][aH * 8], (MLP1 ? g_r1l : g_s2l) + roff, 16);
            size_t boff = ((size_t)grp * RR + bR) * ND + j0 + bS * 8;
            cp16(&Bh[buf][bR][bS * 8], (MLP1 ? g_b1h : g_b2h) + boff, 16);
            cp16(&Bl[buf][bR][bS * 8], (MLP1 ? g_b1l : g_b2l) + boff, 16);
        }
        CP_COMMIT;
    };

    const int warp = tid >> 5, lane = tid & 31;
    const int wm = (warp >> 2) * 64, wn = (warp & 3) * 32;

    float acc[4][4][4];
#pragma unroll
    for (int mt = 0; mt < 4; mt++)
#pragma unroll
        for (int nt = 0; nt < 4; nt++)
#pragma unroll
            for (int q = 0; q < 4; q++) acc[mt][nt][q] = 0.f;

    fill(0, 0);
    const int arow = lane & 15, acol = (lane >> 4) * 8;
    const int bg = lane >> 3;
    const int brow = (bg & 1) * 8 + (lane & 7);

    for (int s = 0; s < S; s++) {
        if (s + 1 < S) fill(s + 1, (s + 1) & 1); else CP_COMMIT;
        CP_WAIT1;
        __syncthreads();
        int buf = s & 1;

        unsigned ah[4][4], al[4][4], bh[4][2], bl[4][2];
#pragma unroll
        for (int mt = 0; mt < 4; mt++) {
            unsigned ad = sm_u32(&Ah[buf][wm + mt * 16 + arow][acol]);
            LDSM_X4(ah[mt][0], ah[mt][1], ah[mt][2], ah[mt][3], ad);
            unsigned ad2 = sm_u32(&Al[buf][wm + mt * 16 + arow][acol]);
            LDSM_X4(al[mt][0], al[mt][1], al[mt][2], al[mt][3], ad2);
        }
#pragma unroll
        for (int np = 0; np < 2; np++) {
            int bcol = wn + (np * 2 + (bg >> 1)) * 8;
            unsigned bd = sm_u32(&Bh[buf][brow][bcol]);
            LDSM_X4T(bh[np * 2][0], bh[np * 2][1], bh[np * 2 + 1][0], bh[np * 2 + 1][1], bd);
            unsigned bd2 = sm_u32(&Bl[buf][brow][bcol]);
            LDSM_X4T(bl[np * 2][0], bl[np * 2][1], bl[np * 2 + 1][0], bl[np * 2 + 1][1], bd2);
        }
#pragma unroll
        for (int mt = 0; mt < 4; mt++)
#pragma unroll
            for (int nt = 0; nt < 4; nt++) MMA16816(acc[mt][nt], ah[mt], bh[nt]);
#pragma unroll
        for (int mt = 0; mt < 4; mt++)
#pragma unroll
            for (int nt = 0; nt < 4; nt++) MMA16816(acc[mt][nt], ah[mt], bl[nt]);
#pragma unroll
        for (int mt = 0; mt < 4; mt++)
#pragma unroll
            for (int nt = 0; nt < 4; nt++) MMA16816(acc[mt][nt], al[mt], bh[nt]);
        __syncthreads();
    }

    // epilogue
#pragma unroll
    for (int mt = 0; mt < 4; mt++) {
#pragma unroll
        for (int nt = 0; nt < 4; nt++) {
            int c0  = wn + nt * 8 + (lane & 3) * 2;
            int col = j0 + c0;
            float bias0 = bias_g[(size_t)e * ND + col];
            float bias1 = bias_g[(size_t)e * ND + col + 1];
#pragma unroll
            for (int hf = 0; hf < 2; hf++) {
                int r = wm + mt * 16 + (lane >> 2) + hf * 8;
                float v0 = acc[mt][nt][hf * 2 + 0] + bias0;
                float v1 = acc[mt][nt][hf * 2 + 1] + bias1;
                if (MLP1) {
                    v0 = gelu_exact(v0); v1 = gelu_exact(v1);
                    bf16 h0, l0, h1, l1;
                    split2(v0, h0, l0); split2(v1, h1, l1);
                    size_t o = (size_t)(row0 + r) * ND + col;
                    *(__nv_bfloat162*)(g_hh + o) = __halves2bfloat162(h0, h1);
                    *(__nv_bfloat162*)(g_hl + o) = __halves2bfloat162(l0, l1);
                } else {
                    int tok = sTok[r];
                    if (tok >= 0) {
                        float gv = sGate[r];
                        atomicAdd(y + (size_t)tok * ND + col,     gv * v0);
                        atomicAdd(y + (size_t)tok * ND + col + 1, gv * v1);
                    }
                }
            }
        }
    }
}

// ---------------- launch ------------------------------------------------------
extern "C" void kernel_launch(void* const* d_in, const int* in_sizes, int n_in,
                              void* d_out, int out_size) {
    const float* x    = (const float*)d_in[0];
    const int*   band = (const int*)d_in[1];
    const float* wg   = (const float*)d_in[2];
    const float* W1   = (const float*)d_in[3];
    const float* b1   = (const float*)d_in[4];
    const float* W2   = (const float*)d_in[5];
    const float* b2   = (const float*)d_in[6];
    const float* A1   = (const float*)d_in[7];
    const float* B1   = (const float*)d_in[8];
    const float* A2   = (const float*)d_in[9];
    const float* B2   = (const float*)d_in[10];
    float* out = (float*)d_out;

    k_init<<<(out_size + 255) / 256, 256>>>(out, out_size);
    k_gate<<<NTOK / 4, 128>>>(x, wg, band);
    k_loss<<<1, 256>>>(out, out_size);
    k_prep<<<(MAXP2 + 255) / 256, 256>>>();
    k_scatter<<<NTOK / 256, 256>>>(band);

    k_split_x <<<(NTOK * DD / 4 + 255) / 256, 256>>>(x);
    k_split_w1<<<(EE * DD * HH / 4 + 255) / 256, 256>>>(W1);
    k_split_w2<<<(EE * HH * OO / 4 + 255) / 256, 256>>>(W2);
    k_split_b1<<<(NG * RR * HH / 4 + 255) / 256, 256>>>(B1);
    k_split_b2<<<(NG * RR * OO / 4 + 255) / 256, 256>>>(B2);

    k_r1<<<RTMAX2, 256>>>(x, A1);
    k_gemm<DD, HH, true ><<<dim3(HH / 128, RTMAX2), 256>>>(b1, nullptr);
    k_s2<<<RTMAX2, 256>>>(A2);
    k_gemm<HH, OO, false><<<dim3(OO / 128, RTMAX2), 256>>>(b2, out);
}

// round 10
// speedup vs baseline: 4.3296x; 1.0145x over previous
#include <cuda_runtime.h>
#include <cuda_bf16.h>
#include <math.h>

typedef __nv_bfloat16 bf16;

#define NTOK 16384
#define DD   1024
#define HH   4096
#define OO   1024
#define EE   8
#define NBANDS 4
#define NG   32            // expert*band groups
#define RR   16
#define MAXP2 36864        // 32768 + 32*128 padding
#define RTMAX2 (MAXP2/128) // 288 row blocks

// ---------------- device scratch ---------------------------------------------
__device__ int   g_e0[NTOK], g_e1[NTOK];
__device__ float g_g0[NTOK], g_g1[NTOK];
__device__ int   g_cntE[EE];
__device__ int   g_cntG[NG];
__device__ int   g_off[NG + 1];
__device__ int   g_cursor[NG];
__device__ int   g_pairTok[MAXP2];
__device__ int   g_pairGrp[MAXP2];
__device__ float g_pairGate[MAXP2];
__device__ bf16  g_r1h[MAXP2 * RR], g_r1l[MAXP2 * RR];
__device__ bf16  g_s2h[MAXP2 * RR], g_s2l[MAXP2 * RR];
__device__ bf16  g_xh[(size_t)NTOK * DD], g_xl[(size_t)NTOK * DD];
__device__ bf16  g_w1h[(size_t)EE * DD * HH], g_w1l[(size_t)EE * DD * HH];
__device__ bf16  g_w2h[(size_t)EE * HH * OO], g_w2l[(size_t)EE * HH * OO];
__device__ bf16  g_b1h[(size_t)NG * RR * HH], g_b1l[(size_t)NG * RR * HH];
__device__ bf16  g_b2h[(size_t)NG * RR * OO], g_b2l[(size_t)NG * RR * OO];
__device__ bf16  g_hh[(size_t)MAXP2 * HH], g_hl[(size_t)MAXP2 * HH];

__device__ __forceinline__ float gelu_exact(float v) {
    return 0.5f * v * (1.0f + erff(v * 0.70710678118654752f));
}
__device__ __forceinline__ void split2(float v, bf16& h, bf16& l) {
    h = __float2bfloat16(v);
    l = __float2bfloat16(v - __bfloat162float(h));
}
__device__ __forceinline__ unsigned sm_u32(const void* p) {
    return (unsigned)__cvta_generic_to_shared(p);
}
__device__ __forceinline__ void cp16(void* d, const void* s, int sz) {
    asm volatile("cp.async.cg.shared.global [%0], [%1], 16, %2;\n"
                 :: "r"(sm_u32(d)), "l"(s), "r"(sz));
}
#define CP_COMMIT asm volatile("cp.async.commit_group;\n")
#define CP_WAIT1  asm volatile("cp.async.wait_group 1;\n")

#define LDSM_X4(R0,R1,R2,R3,ADDR) \
    asm volatile("ldmatrix.sync.aligned.m8n8.x4.shared.b16 {%0,%1,%2,%3}, [%4];\n" \
                 : "=r"(R0),"=r"(R1),"=r"(R2),"=r"(R3) : "r"(ADDR))
#define LDSM_X4T(R0,R1,R2,R3,ADDR) \
    asm volatile("ldmatrix.sync.aligned.m8n8.x4.trans.shared.b16 {%0,%1,%2,%3}, [%4];\n" \
                 : "=r"(R0),"=r"(R1),"=r"(R2),"=r"(R3) : "r"(ADDR))
#define MMA16816(C,A,B) \
    asm volatile("mma.sync.aligned.m16n8k16.row.col.f32.bf16.bf16.f32 " \
                 "{%0,%1,%2,%3},{%4,%5,%6,%7},{%8,%9},{%0,%1,%2,%3};\n" \
                 : "+f"(C[0]),"+f"(C[1]),"+f"(C[2]),"+f"(C[3]) \
                 : "r"(A[0]),"r"(A[1]),"r"(A[2]),"r"(A[3]),"r"(B[0]),"r"(B[1]))

// dynamic smem layout (bytes)
#define ASTRIDE 40
#define BSTRIDE 136
#define AH_OFF  0
#define AL_OFF  (AH_OFF + 2 * 128 * ASTRIDE * 2)
#define BH_OFF  (AL_OFF + 2 * 128 * ASTRIDE * 2)
#define BL_OFF  (BH_OFF + 2 * 32 * BSTRIDE * 2)
#define TOK_OFF (BL_OFF + 2 * 32 * BSTRIDE * 2)
#define GATE_OFF (TOK_OFF + 128 * 4)
#define SMEM_TOTAL (GATE_OFF + 128 * 4)

// ---------------- init --------------------------------------------------------
__global__ void k_init(float* __restrict__ y, int out_size) {
    int i = blockIdx.x * 256 + threadIdx.x;
    if (i < out_size) y[i] = 0.f;
    if (i < EE) g_cntE[i] = 0;
    if (i < NG) g_cntG[i] = 0;
}

// ---------------- gating ------------------------------------------------------
__global__ void k_gate(const float* __restrict__ x, const float* __restrict__ wg,
                       const int* __restrict__ band) {
    int tok  = blockIdx.x * 4 + (threadIdx.x >> 5);
    int lane = threadIdx.x & 31;
    if (tok >= NTOK) return;
    const float* xr = x + (size_t)tok * DD;
    float acc[EE];
#pragma unroll
    for (int e = 0; e < EE; e++) acc[e] = 0.f;
    for (int d = lane; d < DD; d += 32) {
        float xv = xr[d];
        const float* w = wg + d * EE;
#pragma unroll
        for (int e = 0; e < EE; e++) acc[e] += xv * w[e];
    }
#pragma unroll
    for (int e = 0; e < EE; e++)
#pragma unroll
        for (int o = 16; o > 0; o >>= 1) acc[e] += __shfl_xor_sync(0xffffffffu, acc[e], o);
    if (lane == 0) {
        int e0 = 0; float v0 = acc[0];
#pragma unroll
        for (int e = 1; e < EE; e++) if (acc[e] > v0) { v0 = acc[e]; e0 = e; }
        int e1 = -1; float v1 = -INFINITY;
#pragma unroll
        for (int e = 0; e < EE; e++) if (e != e0 && acc[e] > v1) { v1 = acc[e]; e1 = e; }
        float z1 = expf(v1 - v0);
        float den = 1.0f + z1;
        g_e0[tok] = e0; g_e1[tok] = e1;
        g_g0[tok] = 1.0f / den; g_g1[tok] = z1 / den;
        int b = band[tok];
        atomicAdd(&g_cntE[e0], 1); atomicAdd(&g_cntE[e1], 1);
        atomicAdd(&g_cntG[e0 * NBANDS + b], 1);
        atomicAdd(&g_cntG[e1 * NBANDS + b], 1);
    }
}

// ---------------- loss --------------------------------------------------------
__global__ void k_loss(float* __restrict__ out, int out_size) {
    __shared__ float s[EE * 256];
    float acc[EE];
#pragma unroll
    for (int e = 0; e < EE; e++) acc[e] = 0.f;
    for (int t = threadIdx.x; t < NTOK; t += 256) {
        int e0 = g_e0[t], e1 = g_e1[t];
        float g0 = g_g0[t], g1 = g_g1[t];
#pragma unroll
        for (int e = 0; e < EE; e++)
            acc[e] += (e == e0 ? g0 : 0.f) + (e == e1 ? g1 : 0.f);
    }
#pragma unroll
    for (int e = 0; e < EE; e++) s[e * 256 + threadIdx.x] = acc[e];
    __syncthreads();
    for (int st = 128; st > 0; st >>= 1) {
        if (threadIdx.x < st)
#pragma unroll
            for (int e = 0; e < EE; e++)
                s[e * 256 + threadIdx.x] += s[e * 256 + threadIdx.x + st];
        __syncthreads();
    }
    if (threadIdx.x == 0) {
        float imp[EE], ld[EE];
#pragma unroll
        for (int e = 0; e < EE; e++) { imp[e] = s[e * 256]; ld[e] = (float)g_cntE[e]; }
        float m1 = 0.f, m2 = 0.f;
#pragma unroll
        for (int e = 0; e < EE; e++) { m1 += imp[e]; m2 += ld[e]; }
        m1 /= EE; m2 /= EE;
        float v1 = 0.f, v2 = 0.f;
#pragma unroll
        for (int e = 0; e < EE; e++) {
            float d1 = imp[e] - m1, d2 = ld[e] - m2;
            v1 += d1 * d1; v2 += d2 * d2;
        }
        v1 /= (EE - 1); v2 /= (EE - 1);
        out[out_size - 1] = 0.01f * (v1 / (m1 * m1 + 1e-10f) + v2 / (m2 * m2 + 1e-10f));
    }
}

// ---------------- prep + scatter ---------------------------------------------
__global__ void k_prep() {
    int i = blockIdx.x * 256 + threadIdx.x;
    if (i < MAXP2) { g_pairTok[i] = -1; g_pairGrp[i] = 0; g_pairGate[i] = 0.f; }
    if (i == 0) {
        int off = 0;
        for (int g = 0; g < NG; g++) {
            g_off[g] = off; g_cursor[g] = off;
            off += ((g_cntG[g] + 127) >> 7) << 7;
        }
        g_off[NG] = off;
    }
}

__global__ void k_scatter(const int* __restrict__ band) {
    int t = blockIdx.x * 256 + threadIdx.x;
    if (t >= NTOK) return;
    int b = band[t];
    int grp0 = g_e0[t] * NBANDS + b;
    int p0 = atomicAdd(&g_cursor[grp0], 1);
    g_pairTok[p0] = t; g_pairGrp[p0] = grp0; g_pairGate[p0] = g_g0[t];
    int grp1 = g_e1[t] * NBANDS + b;
    int p1 = atomicAdd(&g_cursor[grp1], 1);
    g_pairTok[p1] = t; g_pairGrp[p1] = grp1; g_pairGate[p1] = g_g1[t];
}

// ---------------- fp32 -> bf16 hi/lo split kernels ---------------------------
__device__ __forceinline__ void split_body(const float* __restrict__ src,
                                           bf16* __restrict__ hi, bf16* __restrict__ lo,
                                           int n4) {
    int i = blockIdx.x * 256 + threadIdx.x;
    if (i >= n4) return;
    float4 v = ((const float4*)src)[i];
    bf16 h0, h1, h2, h3, l0, l1, l2, l3;
    split2(v.x, h0, l0); split2(v.y, h1, l1);
    split2(v.z, h2, l2); split2(v.w, h3, l3);
    ((__nv_bfloat162*)hi)[i * 2 + 0] = __halves2bfloat162(h0, h1);
    ((__nv_bfloat162*)hi)[i * 2 + 1] = __halves2bfloat162(h2, h3);
    ((__nv_bfloat162*)lo)[i * 2 + 0] = __halves2bfloat162(l0, l1);
    ((__nv_bfloat162*)lo)[i * 2 + 1] = __halves2bfloat162(l2, l3);
}
__global__ void k_split_x (const float* s) { split_body(s, g_xh,  g_xl,  NTOK * DD / 4); }
__global__ void k_split_w1(const float* s) { split_body(s, g_w1h, g_w1l, EE * DD * HH / 4); }
__global__ void k_split_w2(const float* s) { split_body(s, g_w2h, g_w2l, EE * HH * OO / 4); }
__global__ void k_split_b1(const float* s) { split_body(s, g_b1h, g_b1l, NG * RR * HH / 4); }
__global__ void k_split_b2(const float* s) { split_body(s, g_b2h, g_b2l, NG * RR * OO / 4); }

// ---------------- group id for a row block -----------------------------------
__device__ __forceinline__ int grp_of(int row0) {
    int grp = 0;
#pragma unroll
    for (int i = 1; i < NG; i++) if (row0 >= g_off[i]) grp = i;
    return grp;
}

// ---------------- r1 = 2*(x . A1[grp]) : block-cooperative, smem A ----------
__global__ void __launch_bounds__(256) k_r1(const float* __restrict__ x,
                                            const float* __restrict__ A1) {
    __shared__ float sA[32][RR];
    int row0 = blockIdx.x * 128;
    int grp  = grp_of(row0);
    int tid  = threadIdx.x;
    int row  = tid >> 1;          // 0..127
    int half = tid & 1;           // r in [half*8, half*8+8)
    int tok  = g_pairTok[row0 + row];
    const float* A = A1 + (size_t)grp * DD * RR;

    float acc[8];
#pragma unroll
    for (int q = 0; q < 8; q++) acc[q] = 0.f;

    for (int k0 = 0; k0 < DD; k0 += 32) {
        int kk = tid >> 3, rp = tid & 7;
        *(float2*)&sA[kk][rp * 2] = *(const float2*)(A + (size_t)(k0 + kk) * RR + rp * 2);
        __syncthreads();
        if (tok >= 0) {
            const float* xr = x + (size_t)tok * DD + k0;
#pragma unroll
            for (int k = 0; k < 32; k++) {
                float xv = xr[k];
                float4 a0 = *(const float4*)&sA[k][half * 8];
                float4 a1 = *(const float4*)&sA[k][half * 8 + 4];
                acc[0] += xv * a0.x; acc[1] += xv * a0.y;
                acc[2] += xv * a0.z; acc[3] += xv * a0.w;
                acc[4] += xv * a1.x; acc[5] += xv * a1.y;
                acc[6] += xv * a1.z; acc[7] += xv * a1.w;
            }
        }
        __syncthreads();
    }
#pragma unroll
    for (int q = 0; q < 8; q++) {
        bf16 h, l; split2(2.0f * acc[q], h, l);
        size_t o = (size_t)(row0 + row) * RR + half * 8 + q;
        g_r1h[o] = h; g_r1l[o] = l;
    }
}

// ---------------- s2 = 2*(h . A2[grp]) : block-cooperative, smem A -----------
__global__ void __launch_bounds__(256) k_s2(const float* __restrict__ A2) {
    __shared__ float sA[32][RR];
    int row0 = blockIdx.x * 128;
    int grp  = grp_of(row0);
    int tid  = threadIdx.x;
    int row  = tid >> 1;
    int half = tid & 1;
    const float* A = A2 + (size_t)grp * HH * RR;
    const __nv_bfloat162* hh = (const __nv_bfloat162*)(g_hh + (size_t)(row0 + row) * HH);
    const __nv_bfloat162* hl = (const __nv_bfloat162*)(g_hl + (size_t)(row0 + row) * HH);

    float acc[8];
#pragma unroll
    for (int q = 0; q < 8; q++) acc[q] = 0.f;

    for (int k0 = 0; k0 < HH; k0 += 32) {
        int kk = tid >> 3, rp = tid & 7;
        *(float2*)&sA[kk][rp * 2] = *(const float2*)(A + (size_t)(k0 + kk) * RR + rp * 2);
        __syncthreads();
#pragma unroll
        for (int k2 = 0; k2 < 16; k2++) {
            __nv_bfloat162 vh = hh[k0 / 2 + k2];
            __nv_bfloat162 vl = hl[k0 / 2 + k2];
            float hv0 = __bfloat162float(vh.x) + __bfloat162float(vl.x);
            float hv1 = __bfloat162float(vh.y) + __bfloat162float(vl.y);
#pragma unroll
            for (int pair = 0; pair < 2; pair++) {
                float xv = pair ? hv1 : hv0;
                int k = k2 * 2 + pair;
                float4 a0 = *(const float4*)&sA[k][half * 8];
                float4 a1 = *(const float4*)&sA[k][half * 8 + 4];
                acc[0] += xv * a0.x; acc[1] += xv * a0.y;
                acc[2] += xv * a0.z; acc[3] += xv * a0.w;
                acc[4] += xv * a1.x; acc[5] += xv * a1.y;
                acc[6] += xv * a1.z; acc[7] += xv * a1.w;
            }
        }
        __syncthreads();
    }
#pragma unroll
    for (int q = 0; q < 8; q++) {
        bf16 h, l; split2(2.0f * acc[q], h, l);
        size_t o = (size_t)(row0 + row) * RR + half * 8 + q;
        g_s2h[o] = h; g_s2l[o] = l;
    }
}

// ---------------- tensor-core GEMM (split bf16, 3-term), BK=32 stages --------
// Dynamic smem; grid x = column tiles (fast) for A-operand L2 locality.
template<int KD, int ND, bool MLP1>
__global__ void __launch_bounds__(256) k_gemm(const float* __restrict__ bias_g,
                                              float* __restrict__ y) {
    extern __shared__ char smem[];
    bf16*  sAh   = (bf16*)(smem + AH_OFF);
    bf16*  sAl   = (bf16*)(smem + AL_OFF);
    bf16*  sBh   = (bf16*)(smem + BH_OFF);
    bf16*  sBl   = (bf16*)(smem + BL_OFF);
    int*   sTok  = (int*)(smem + TOK_OFF);
    float* sGate = (float*)(smem + GATE_OFF);

    int row0 = blockIdx.y * 128;
    if (row0 >= g_off[NG]) return;
    int grp = grp_of(row0);
    int e  = grp >> 2;
    int j0 = blockIdx.x * 128;
    int tid = threadIdx.x;

    if (tid < 128) {
        sTok[tid]  = g_pairTok[row0 + tid];
        sGate[tid] = g_pairGate[row0 + tid];
    }
    __syncthreads();

    const bf16* Asrc_h = MLP1 ? g_xh  : g_hh;
    const bf16* Asrc_l = MLP1 ? g_xl  : g_hl;
    const bf16* Wsrc_h = MLP1 ? g_w1h : g_w2h;
    const bf16* Wsrc_l = MLP1 ? g_w1l : g_w2l;
    const bf16* Rsrc_h = MLP1 ? g_r1h : g_s2h;
    const bf16* Rsrc_l = MLP1 ? g_r1l : g_s2l;
    const bf16* Lsrc_h = MLP1 ? g_b1h : g_b2h;
    const bf16* Lsrc_l = MLP1 ? g_b1l : g_b2l;

    const int SM32 = KD / 32;
    const int S    = SM32 + 1;   // + LoRA stage (16 wide)

    // main-stage fill: A 128x32, B 32x128 (hi+lo)
    auto fillMain = [&](int s, int buf) {
        int k0 = s * 32;
        int r  = tid >> 1;
        size_t aoff; int sz = 16;
        if (MLP1) {
            int tok = sTok[r];
            sz = tok >= 0 ? 16 : 0;
            aoff = (size_t)(tok >= 0 ? tok : 0) * KD + k0;
        } else {
            aoff = (size_t)(row0 + r) * KD + k0;
        }
        bf16* dAh = sAh + (buf * 128 + r) * ASTRIDE;
        bf16* dAl = sAl + (buf * 128 + r) * ASTRIDE;
#pragma unroll
        for (int q = 0; q < 2; q++) {
            int c = (tid & 1) * 2 + q;            // 0..3
            cp16(dAh + c * 8, Asrc_h + aoff + c * 8, sz);
            cp16(dAl + c * 8, Asrc_l + aoff + c * 8, sz);
        }
        int br = tid >> 3;
        size_t woff = (size_t)e * ((size_t)KD * ND) + (size_t)(k0 + br) * ND + j0;
        bf16* dBh = sBh + (buf * 32 + br) * BSTRIDE;
        bf16* dBl = sBl + (buf * 32 + br) * BSTRIDE;
#pragma unroll
        for (int q = 0; q < 2; q++) {
            int c = (tid & 7) * 2 + q;            // 0..15
            cp16(dBh + c * 8, Wsrc_h + woff + c * 8, 16);
            cp16(dBl + c * 8, Wsrc_l + woff + c * 8, 16);
        }
        CP_COMMIT;
    };
    // LoRA fill: A 128x16, B 16x128
    auto fillLora = [&](int buf) {
        int r = tid >> 1, seg = tid & 1;
        size_t roff = (size_t)(row0 + r) * RR + seg * 8;
        cp16(sAh + (buf * 128 + r) * ASTRIDE + seg * 8, Rsrc_h + roff, 16);
        cp16(sAl + (buf * 128 + r) * ASTRIDE + seg * 8, Rsrc_l + roff, 16);
        int br = tid >> 4, c = tid & 15;
        size_t boff = ((size_t)grp * RR + br) * ND + j0 + c * 8;
        cp16(sBh + (buf * 32 + br) * BSTRIDE + c * 8, Lsrc_h + boff, 16);
        cp16(sBl + (buf * 32 + br) * BSTRIDE + c * 8, Lsrc_l + boff, 16);
        CP_COMMIT;
    };

    const int warp = tid >> 5, lane = tid & 31;
    const int wm = (warp >> 2) * 64, wn = (warp & 3) * 32;

    float acc[4][4][4];
#pragma unroll
    for (int mt = 0; mt < 4; mt++)
#pragma unroll
        for (int nt = 0; nt < 4; nt++)
#pragma unroll
            for (int q = 0; q < 4; q++) acc[mt][nt][q] = 0.f;

    fillMain(0, 0);
    const int arow = lane & 15, acol = (lane >> 4) * 8;
    const int bg = lane >> 3;
    const int brow = (bg & 1) * 8 + (lane & 7);

    for (int s = 0; s < S; s++) {
        if (s + 1 < SM32)       fillMain(s + 1, (s + 1) & 1);
        else if (s + 1 == SM32) fillLora((s + 1) & 1);
        else                    CP_COMMIT;
        CP_WAIT1;
        __syncthreads();
        int buf = s & 1;
        int nh  = (s == SM32) ? 1 : 2;

        for (int kh = 0; kh < nh; kh++) {
            unsigned ah[4][4], al[4][4], bh[4][2], bl[4][2];
#pragma unroll
            for (int mt = 0; mt < 4; mt++) {
                unsigned ad = sm_u32(sAh + (buf * 128 + wm + mt * 16 + arow) * ASTRIDE + kh * 16 + acol);
                LDSM_X4(ah[mt][0], ah[mt][1], ah[mt][2], ah[mt][3], ad);
                unsigned ad2 = sm_u32(sAl + (buf * 128 + wm + mt * 16 + arow) * ASTRIDE + kh * 16 + acol);
                LDSM_X4(al[mt][0], al[mt][1], al[mt][2], al[mt][3], ad2);
            }
#pragma unroll
            for (int np = 0; np < 2; np++) {
                int bcol = wn + (np * 2 + (bg >> 1)) * 8;
                unsigned bd = sm_u32(sBh + (buf * 32 + kh * 16 + brow) * BSTRIDE + bcol);
                LDSM_X4T(bh[np * 2][0], bh[np * 2][1], bh[np * 2 + 1][0], bh[np * 2 + 1][1], bd);
                unsigned bd2 = sm_u32(sBl + (buf * 32 + kh * 16 + brow) * BSTRIDE + bcol);
                LDSM_X4T(bl[np * 2][0], bl[np * 2][1], bl[np * 2 + 1][0], bl[np * 2 + 1][1], bd2);
            }
#pragma unroll
            for (int mt = 0; mt < 4; mt++)
#pragma unroll
                for (int nt = 0; nt < 4; nt++) MMA16816(acc[mt][nt], ah[mt], bh[nt]);
#pragma unroll
            for (int mt = 0; mt < 4; mt++)
#pragma unroll
                for (int nt = 0; nt < 4; nt++) MMA16816(acc[mt][nt], ah[mt], bl[nt]);
#pragma unroll
            for (int mt = 0; mt < 4; mt++)
#pragma unroll
                for (int nt = 0; nt < 4; nt++) MMA16816(acc[mt][nt], al[mt], bh[nt]);
        }
        __syncthreads();
    }

    // epilogue
#pragma unroll
    for (int mt = 0; mt < 4; mt++) {
#pragma unroll
        for (int nt = 0; nt < 4; nt++) {
            int c0  = wn + nt * 8 + (lane & 3) * 2;
            int col = j0 + c0;
            float bias0 = bias_g[(size_t)e * ND + col];
            float bias1 = bias_g[(size_t)e * ND + col + 1];
#pragma unroll
            for (int hf = 0; hf < 2; hf++) {
                int r = wm + mt * 16 + (lane >> 2) + hf * 8;
                float v0 = acc[mt][nt][hf * 2 + 0] + bias0;
                float v1 = acc[mt][nt][hf * 2 + 1] + bias1;
                if (MLP1) {
                    v0 = gelu_exact(v0); v1 = gelu_exact(v1);
                    bf16 h0, l0, h1, l1;
                    split2(v0, h0, l0); split2(v1, h1, l1);
                    size_t o = (size_t)(row0 + r) * ND + col;
                    *(__nv_bfloat162*)(g_hh + o) = __halves2bfloat162(h0, h1);
                    *(__nv_bfloat162*)(g_hl + o) = __halves2bfloat162(l0, l1);
                } else {
                    int tok = sTok[r];
                    if (tok >= 0) {
                        float gv = sGate[r];
                        atomicAdd(y + (size_t)tok * ND + col,     gv * v0);
                        atomicAdd(y + (size_t)tok * ND + col + 1, gv * v1);
                    }
                }
            }
        }
    }
}

// ---------------- launch ------------------------------------------------------
extern "C" void kernel_launch(void* const* d_in, const int* in_sizes, int n_in,
                              void* d_out, int out_size) {
    const float* x    = (const float*)d_in[0];
    const int*   band = (const int*)d_in[1];
    const float* wg   = (const float*)d_in[2];
    const float* W1   = (const float*)d_in[3];
    const float* b1   = (const float*)d_in[4];
    const float* W2   = (const float*)d_in[5];
    const float* b2   = (const float*)d_in[6];
    const float* A1   = (const float*)d_in[7];
    const float* B1   = (const float*)d_in[8];
    const float* A2   = (const float*)d_in[9];
    const float* B2   = (const float*)d_in[10];
    float* out = (float*)d_out;

    cudaFuncSetAttribute(k_gemm<DD, HH, true >,
                         cudaFuncAttributeMaxDynamicSharedMemorySize, SMEM_TOTAL);
    cudaFuncSetAttribute(k_gemm<HH, OO, false>,
                         cudaFuncAttributeMaxDynamicSharedMemorySize, SMEM_TOTAL);

    k_init<<<(out_size + 255) / 256, 256>>>(out, out_size);
    k_gate<<<NTOK / 4, 128>>>(x, wg, band);
    k_loss<<<1, 256>>>(out, out_size);
    k_prep<<<(MAXP2 + 255) / 256, 256>>>();
    k_scatter<<<NTOK / 256, 256>>>(band);

    k_split_x <<<(NTOK * DD / 4 + 255) / 256, 256>>>(x);
    k_split_w1<<<(EE * DD * HH / 4 + 255) / 256, 256>>>(W1);
    k_split_w2<<<(EE * HH * OO / 4 + 255) / 256, 256>>>(W2);
    k_split_b1<<<(NG * RR * HH / 4 + 255) / 256, 256>>>(B1);
    k_split_b2<<<(NG * RR * OO / 4 + 255) / 256, 256>>>(B2);

    k_r1<<<RTMAX2, 256>>>(x, A1);
    k_gemm<DD, HH, true ><<<dim3(HH / 128, RTMAX2), 256, SMEM_TOTAL>>>(b1, nullptr);
    k_s2<<<RTMAX2, 256>>>(A2);
    k_gemm<HH, OO, false><<<dim3(OO / 128, RTMAX2), 256, SMEM_TOTAL>>>(b2, out);
}